// round 2
// baseline (speedup 1.0000x reference)
#include <cuda_runtime.h>
#include <math.h>

#define BSZ    2
#define SEQ    2048
#define HID    2048
#define NH     16
#define HD     128
#define MROWS  (BSZ*SEQ)          // 4096
#define NEGBIG (-1000000000.0f)

// ---------------- scratch (device globals; no allocations allowed) ----------
__device__ float g_Q  [MROWS*HID];
__device__ float g_K  [MROWS*HID];
__device__ float g_V  [MROWS*HID];
__device__ float g_CTX[MROWS*HID];
__device__ float g_cos[SEQ*64];
__device__ float g_sin[SEQ*64];

// ---------------- GEMM: C[M,N] = A[M,K] @ B[N,K]^T, all row-major -----------
#define BM 128
#define BN 128
#define BK 16
#define TM 8
#define TN 8

__global__ __launch_bounds__(256) void gemm_nt_kernel(
    const float* __restrict__ A, const float* __restrict__ B,
    float* __restrict__ C, int M, int N, int K)
{
    __shared__ float As[BK][BM + 4];
    __shared__ float Bs[BK][BN + 4];

    const int tid = threadIdx.x;
    const int m0 = blockIdx.y * BM;
    const int n0 = blockIdx.x * BN;
    const int ty = tid >> 4;        // 0..15
    const int tx = tid & 15;        // 0..15

    const float* Ab = A + (size_t)m0 * K;
    const float* Bb = B + (size_t)n0 * K;

    float acc[TM][TN];
#pragma unroll
    for (int i = 0; i < TM; i++)
#pragma unroll
        for (int j = 0; j < TN; j++) acc[i][j] = 0.0f;

    for (int k0 = 0; k0 < K; k0 += BK) {
        // load 128x16 tiles of A and B (transposed into smem), 2 float4 each
#pragma unroll
        for (int i = 0; i < 2; i++) {
            int f4  = tid + i * 256;
            int row = f4 >> 2;
            int kq  = (f4 & 3) << 2;
            float4 a = *(const float4*)(Ab + (size_t)row * K + k0 + kq);
            As[kq + 0][row] = a.x; As[kq + 1][row] = a.y;
            As[kq + 2][row] = a.z; As[kq + 3][row] = a.w;
            float4 b = *(const float4*)(Bb + (size_t)row * K + k0 + kq);
            Bs[kq + 0][row] = b.x; Bs[kq + 1][row] = b.y;
            Bs[kq + 2][row] = b.z; Bs[kq + 3][row] = b.w;
        }
        __syncthreads();

#pragma unroll
        for (int k = 0; k < BK; k++) {
            float ra[TM], rb[TN];
            *(float4*)&ra[0] = *(const float4*)&As[k][ty * TM];
            *(float4*)&ra[4] = *(const float4*)&As[k][ty * TM + 4];
            *(float4*)&rb[0] = *(const float4*)&Bs[k][tx * TN];
            *(float4*)&rb[4] = *(const float4*)&Bs[k][tx * TN + 4];
#pragma unroll
            for (int i = 0; i < TM; i++)
#pragma unroll
                for (int j = 0; j < TN; j++)
                    acc[i][j] = fmaf(ra[i], rb[j], acc[i][j]);
        }
        __syncthreads();
    }

    const int crow0 = m0 + ty * TM;
    const int ccol0 = n0 + tx * TN;
#pragma unroll
    for (int i = 0; i < TM; i++) {
        float4 s0 = make_float4(acc[i][0], acc[i][1], acc[i][2], acc[i][3]);
        float4 s1 = make_float4(acc[i][4], acc[i][5], acc[i][6], acc[i][7]);
        *(float4*)(C + (size_t)(crow0 + i) * N + ccol0)     = s0;
        *(float4*)(C + (size_t)(crow0 + i) * N + ccol0 + 4) = s1;
    }
}

// ---------------- RoPE tables (double precision, fast-math-proof) -----------
__global__ void rope_table_kernel()
{
    int t = blockIdx.x;      // 0..SEQ-1
    int i = threadIdx.x;     // 0..63
    double invf = exp(-((double)i / 64.0) * log(10000.0));
    double ang  = (double)t * invf;
    double sd, cd;
    sincos(ang, &sd, &cd);
    g_cos[t * 64 + i] = (float)cd;
    g_sin[t * 64 + i] = (float)sd;
}

// ---------------- RoPE apply (in-place on Q/K, layout [b,s,h,d]) ------------
__global__ __launch_bounds__(256) void rope_apply_kernel(const int* __restrict__ pos)
{
    int gid  = blockIdx.x * 256 + threadIdx.x;   // over MROWS*NH*64
    int i    = gid & 63;
    int hrow = gid >> 6;                         // (b*SEQ+s)*NH + h
    int s    = (hrow / NH) % SEQ;
    int p    = pos[s];
    float c  = g_cos[p * 64 + i];
    float sn = g_sin[p * 64 + i];
    float* ptr = (blockIdx.y ? g_K : g_Q) + (size_t)hrow * HD;
    float x1 = ptr[i];
    float x2 = ptr[i + 64];
    ptr[i]      = x1 * c - x2 * sn;
    ptr[i + 64] = x2 * c + x1 * sn;
}

// ---------------- Flash attention (fp32, causal, online softmax) ------------
// grid: (SEQ/64, BSZ*NH), 256 threads.
// smem: Qs[64][132] + KVs[64][132] + Pst[64][68]  = 84992 B (dynamic)
#define FBM 64
#define FBN 64
#define QPITCH 132
#define PPITCH 68
#define FLASH_SMEM ((FBM*QPITCH*2 + FBN*PPITCH) * sizeof(float))

__global__ __launch_bounds__(256) void flash_kernel(
    const float* __restrict__ Q, const float* __restrict__ K,
    const float* __restrict__ V, float* __restrict__ CTX)
{
    extern __shared__ float sm[];
    float* Qs  = sm;                       // [64][132]
    float* KVs = sm + FBM * QPITCH;        // [64][132]
    float* Pst = KVs + FBM * QPITCH;       // [64][68]  P transposed: [col][row]

    const int tid = threadIdx.x;
    const int b   = blockIdx.y / NH;
    const int h   = blockIdx.y % NH;
    const int qt  = blockIdx.x;
    const int qm0 = qt * FBM;

    const int trow = tid >> 4;   // 0..15 -> rows trow*4..+3
    const int tcol = tid & 15;   // 0..15 -> score cols tcol*4..+3, out dims tcol*8..+7

    const float scale = 0.08838834764831845f;   // 1/sqrt(128)

    // load Q tile (scaled)
#pragma unroll
    for (int i = 0; i < 8; i++) {
        int f4  = tid + i * 256;
        int row = f4 >> 5;
        int col = (f4 & 31) << 2;
        size_t g = ((size_t)(b * SEQ + qm0 + row) * NH + h) * HD + col;
        float4 v = *(const float4*)(Q + g);
        v.x *= scale; v.y *= scale; v.z *= scale; v.w *= scale;
        *(float4*)&Qs[row * QPITCH + col] = v;
    }

    float m_i[4], l_i[4], accv[4][8];
#pragma unroll
    for (int i = 0; i < 4; i++) {
        m_i[i] = -3.0e38f; l_i[i] = 0.0f;
#pragma unroll
        for (int j = 0; j < 8; j++) accv[i][j] = 0.0f;
    }

    __syncthreads();

    for (int kt = 0; kt <= qt; kt++) {
        const int kn0 = kt * FBN;
        // load K tile
#pragma unroll
        for (int i = 0; i < 8; i++) {
            int f4  = tid + i * 256;
            int row = f4 >> 5;
            int col = (f4 & 31) << 2;
            size_t g = ((size_t)(b * SEQ + kn0 + row) * NH + h) * HD + col;
            *(float4*)&KVs[row * QPITCH + col] = *(const float4*)(K + g);
        }
        __syncthreads();

        // scores 4x4 per thread
        float sv[4][4];
#pragma unroll
        for (int i = 0; i < 4; i++)
#pragma unroll
            for (int j = 0; j < 4; j++) sv[i][j] = 0.0f;

        for (int d4 = 0; d4 < HD; d4 += 4) {
            float4 qv[4], kv[4];
#pragma unroll
            for (int i = 0; i < 4; i++)
                qv[i] = *(const float4*)&Qs[(trow * 4 + i) * QPITCH + d4];
#pragma unroll
            for (int j = 0; j < 4; j++)
                kv[j] = *(const float4*)&KVs[(tcol * 4 + j) * QPITCH + d4];
#pragma unroll
            for (int i = 0; i < 4; i++)
#pragma unroll
                for (int j = 0; j < 4; j++) {
                    sv[i][j] = fmaf(qv[i].x, kv[j].x, sv[i][j]);
                    sv[i][j] = fmaf(qv[i].y, kv[j].y, sv[i][j]);
                    sv[i][j] = fmaf(qv[i].z, kv[j].z, sv[i][j]);
                    sv[i][j] = fmaf(qv[i].w, kv[j].w, sv[i][j]);
                }
        }

        // causal mask (diagonal tile only)
        if (kt == qt) {
#pragma unroll
            for (int i = 0; i < 4; i++) {
                int qr = qm0 + trow * 4 + i;
#pragma unroll
                for (int j = 0; j < 4; j++) {
                    int kc = kn0 + tcol * 4 + j;
                    if (kc > qr) sv[i][j] += NEGBIG;
                }
            }
        }

        // online softmax update
        float p[4][4];
#pragma unroll
        for (int i = 0; i < 4; i++) {
            float rm = fmaxf(fmaxf(sv[i][0], sv[i][1]), fmaxf(sv[i][2], sv[i][3]));
#pragma unroll
            for (int off = 8; off > 0; off >>= 1)
                rm = fmaxf(rm, __shfl_xor_sync(0xffffffffu, rm, off));
            float mnew = fmaxf(m_i[i], rm);
            float corr = __expf(m_i[i] - mnew);
            float rs = 0.0f;
#pragma unroll
            for (int j = 0; j < 4; j++) {
                p[i][j] = __expf(sv[i][j] - mnew);
                rs += p[i][j];
            }
#pragma unroll
            for (int off = 8; off > 0; off >>= 1)
                rs += __shfl_xor_sync(0xffffffffu, rs, off);
            l_i[i] = l_i[i] * corr + rs;
            m_i[i] = mnew;
#pragma unroll
            for (int j = 0; j < 8; j++) accv[i][j] *= corr;
        }

        // store P transposed: Pst[col][row]
#pragma unroll
        for (int j = 0; j < 4; j++)
#pragma unroll
            for (int i = 0; i < 4; i++)
                Pst[(tcol * 4 + j) * PPITCH + trow * 4 + i] = p[i][j];

        __syncthreads();

        // load V tile over KVs
#pragma unroll
        for (int i = 0; i < 8; i++) {
            int f4  = tid + i * 256;
            int row = f4 >> 5;
            int col = (f4 & 31) << 2;
            size_t g = ((size_t)(b * SEQ + kn0 + row) * NH + h) * HD + col;
            *(float4*)&KVs[row * QPITCH + col] = *(const float4*)(V + g);
        }
        __syncthreads();

        // PV accumulate: rows trow*4..+3, dims tcol*8..+7
        for (int c = 0; c < FBN; c++) {
            float4 pv = *(const float4*)&Pst[c * PPITCH + trow * 4];
            float4 v0 = *(const float4*)&KVs[c * QPITCH + tcol * 8];
            float4 v1 = *(const float4*)&KVs[c * QPITCH + tcol * 8 + 4];
            float pr[4] = {pv.x, pv.y, pv.z, pv.w};
#pragma unroll
            for (int i = 0; i < 4; i++) {
                accv[i][0] = fmaf(pr[i], v0.x, accv[i][0]);
                accv[i][1] = fmaf(pr[i], v0.y, accv[i][1]);
                accv[i][2] = fmaf(pr[i], v0.z, accv[i][2]);
                accv[i][3] = fmaf(pr[i], v0.w, accv[i][3]);
                accv[i][4] = fmaf(pr[i], v1.x, accv[i][4]);
                accv[i][5] = fmaf(pr[i], v1.y, accv[i][5]);
                accv[i][6] = fmaf(pr[i], v1.z, accv[i][6]);
                accv[i][7] = fmaf(pr[i], v1.w, accv[i][7]);
            }
        }
        __syncthreads();   // protect KVs before next K load
    }

    // epilogue: O = acc / l  -> CTX [b,s,h,d]
#pragma unroll
    for (int i = 0; i < 4; i++) {
        float inv = 1.0f / l_i[i];
        int qr = qm0 + trow * 4 + i;
        size_t g = ((size_t)(b * SEQ + qr) * NH + h) * HD + tcol * 8;
        float4 o0 = make_float4(accv[i][0]*inv, accv[i][1]*inv, accv[i][2]*inv, accv[i][3]*inv);
        float4 o1 = make_float4(accv[i][4]*inv, accv[i][5]*inv, accv[i][6]*inv, accv[i][7]*inv);
        *(float4*)(CTX + g)     = o0;
        *(float4*)(CTX + g + 4) = o1;
    }
}

// ---------------- launch --------------------------------------------------
extern "C" void kernel_launch(void* const* d_in, const int* in_sizes, int n_in,
                              void* d_out, int out_size)
{
    const float* hs = (const float*)d_in[0];
    const float* Wq = (const float*)d_in[1];
    const float* Wk = (const float*)d_in[2];
    const float* Wv = (const float*)d_in[3];
    const float* Wo = (const float*)d_in[4];
    const int*   pos = (const int*)d_in[6];
    float* out = (float*)d_out;

    float *Qp, *Kp, *Vp, *Cp;
    cudaGetSymbolAddress((void**)&Qp, g_Q);
    cudaGetSymbolAddress((void**)&Kp, g_K);
    cudaGetSymbolAddress((void**)&Vp, g_V);
    cudaGetSymbolAddress((void**)&Cp, g_CTX);

    cudaFuncSetAttribute(flash_kernel,
                         cudaFuncAttributeMaxDynamicSharedMemorySize,
                         (int)FLASH_SMEM);

    dim3 ggrid(HID / BN, MROWS / BM);   // (16, 32)
    dim3 gblk(256);

    gemm_nt_kernel<<<ggrid, gblk>>>(hs, Wq, Qp, MROWS, HID, HID);
    gemm_nt_kernel<<<ggrid, gblk>>>(hs, Wk, Kp, MROWS, HID, HID);
    gemm_nt_kernel<<<ggrid, gblk>>>(hs, Wv, Vp, MROWS, HID, HID);

    rope_table_kernel<<<SEQ, 64>>>();
    rope_apply_kernel<<<dim3((MROWS * NH * 64) / 256, 2), 256>>>(pos);

    flash_kernel<<<dim3(SEQ / FBM, BSZ * NH), 256, FLASH_SMEM>>>(Qp, Kp, Vp, Cp);

    gemm_nt_kernel<<<ggrid, gblk>>>(Cp, Wo, out, MROWS, HID, HID);
}

// round 5
// speedup vs baseline: 1.5672x; 1.5672x over previous
#include <cuda_runtime.h>
#include <cuda_bf16.h>
#include <stdint.h>
#include <math.h>

#define BSZ    2
#define SEQ    2048
#define HID    2048
#define NH     16
#define HD     128
#define MROWS  (BSZ*SEQ)          // 4096
#define NEGBIG (-1000000000.0f)

// ---------------- scratch (device globals; no allocations allowed) ----------
__device__ float g_Q  [MROWS*HID];
__device__ float g_K  [MROWS*HID];
__device__ float g_V  [MROWS*HID];
__device__ float g_CTX[MROWS*HID];
__device__ float g_cos[SEQ*64];
__device__ float g_sin[SEQ*64];

// =====================================================================
// GEMM: C[M,N] = A[M,K] @ B[N,K]^T  via bf16 hi/lo split on tensor cores
// Block tile 128x128x32, 8 warps, warp tile 64x32, double-buffered smem.
// =====================================================================
#define GBM 128
#define GBN 128
#define GBK 32
#define GP  40                       // smem pitch in halves (bank-conflict-free)
#define GPLANE (128*GP)              // halves per plane
#define GSTAGE (4*GPLANE)            // A_hi, A_lo, B_hi, B_lo
#define GEMM_SMEM (2*GSTAGE*sizeof(__nv_bfloat16))   // 81920 B

__device__ __forceinline__ uint32_t pk_hi(float x, float y) {
    __nv_bfloat162 t = __floats2bfloat162_rn(x, y);
    return *(uint32_t*)&t;
}
__device__ __forceinline__ float bf16_res(float x) {
    return x - __bfloat162float(__float2bfloat16(x));
}
__device__ __forceinline__ uint32_t pk_lo(float x, float y) {
    __nv_bfloat162 t = __floats2bfloat162_rn(bf16_res(x), bf16_res(y));
    return *(uint32_t*)&t;
}

__device__ __forceinline__ void mma16816(float* c, const uint32_t* a, const uint32_t* b) {
    asm volatile(
        "mma.sync.aligned.m16n8k16.row.col.f32.bf16.bf16.f32 "
        "{%0,%1,%2,%3}, {%4,%5,%6,%7}, {%8,%9}, {%0,%1,%2,%3};\n"
        : "+f"(c[0]), "+f"(c[1]), "+f"(c[2]), "+f"(c[3])
        : "r"(a[0]), "r"(a[1]), "r"(a[2]), "r"(a[3]), "r"(b[0]), "r"(b[1]));
}

__global__ __launch_bounds__(256) void gemm_bf16x2_nt(
    const float* __restrict__ A, const float* __restrict__ B,
    float* __restrict__ C, int M, int N, int K)
{
    extern __shared__ __align__(16) __nv_bfloat16 gsm[];

    const int tid  = threadIdx.x;
    const int wid  = tid >> 5;
    const int lane = tid & 31;
    const int gid  = lane >> 2;     // 0..7
    const int tig  = lane & 3;      // 0..3

    const int m0 = blockIdx.y * GBM;
    const int n0 = blockIdx.x * GBN;
    const int m0w = (wid & 1) * 64;
    const int n0w = (wid >> 1) * 32;

    // global load assignment: 1024 float4 per tile (128 rows x 8 float4)
    const int lrow = tid >> 3;            // 0..31 (+32*i)
    const int lcol = (tid & 7) << 2;      // 0,4,...,28

    const float* Ab = A + (size_t)(m0 + lrow) * K + lcol;
    const float* Bb = B + (size_t)(n0 + lrow) * K + lcol;

    float acc[4][4][4];
#pragma unroll
    for (int i = 0; i < 4; i++)
#pragma unroll
        for (int j = 0; j < 4; j++)
#pragma unroll
            for (int r = 0; r < 4; r++) acc[i][j][r] = 0.0f;

    const int NIT = K / GBK;   // 64
    float4 ra[4], rb[4];

    // prologue load (k0 = 0)
#pragma unroll
    for (int i = 0; i < 4; i++) {
        ra[i] = *(const float4*)(Ab + (size_t)(32 * i) * K);
        rb[i] = *(const float4*)(Bb + (size_t)(32 * i) * K);
    }
    {
        __nv_bfloat16* Ah = gsm;                 // stage 0
        __nv_bfloat16* Al = gsm + GPLANE;
        __nv_bfloat16* Bh = gsm + 2 * GPLANE;
        __nv_bfloat16* Bl = gsm + 3 * GPLANE;
#pragma unroll
        for (int i = 0; i < 4; i++) {
            int off = (lrow + 32 * i) * GP + lcol;
            *(uint2*)&Ah[off] = make_uint2(pk_hi(ra[i].x, ra[i].y), pk_hi(ra[i].z, ra[i].w));
            *(uint2*)&Al[off] = make_uint2(pk_lo(ra[i].x, ra[i].y), pk_lo(ra[i].z, ra[i].w));
            *(uint2*)&Bh[off] = make_uint2(pk_hi(rb[i].x, rb[i].y), pk_hi(rb[i].z, rb[i].w));
            *(uint2*)&Bl[off] = make_uint2(pk_lo(rb[i].x, rb[i].y), pk_lo(rb[i].z, rb[i].w));
        }
    }
    __syncthreads();

    for (int it = 0; it < NIT; ++it) {
        // prefetch next tile into registers
        if (it + 1 < NIT) {
            int k0 = (it + 1) * GBK;
#pragma unroll
            for (int i = 0; i < 4; i++) {
                ra[i] = *(const float4*)(Ab + (size_t)(32 * i) * K + k0);
                rb[i] = *(const float4*)(Bb + (size_t)(32 * i) * K + k0);
            }
        }

        // compute on stage it&1
        {
            const __nv_bfloat16* base = gsm + (size_t)(it & 1) * GSTAGE;
            const __nv_bfloat16* Ah = base;
            const __nv_bfloat16* Al = base + GPLANE;
            const __nv_bfloat16* Bh = base + 2 * GPLANE;
            const __nv_bfloat16* Bl = base + 3 * GPLANE;

#pragma unroll
            for (int ks = 0; ks < 2; ks++) {
                const int kb = ks * 16;
                uint32_t afh[4][4], afl[4][4], bfh[4][2], bfl[4][2];
#pragma unroll
                for (int mi = 0; mi < 4; mi++) {
                    int r0 = m0w + mi * 16 + gid;
                    int c0 = kb + tig * 2;
                    afh[mi][0] = *(const uint32_t*)&Ah[r0 * GP + c0];
                    afh[mi][1] = *(const uint32_t*)&Ah[(r0 + 8) * GP + c0];
                    afh[mi][2] = *(const uint32_t*)&Ah[r0 * GP + c0 + 8];
                    afh[mi][3] = *(const uint32_t*)&Ah[(r0 + 8) * GP + c0 + 8];
                    afl[mi][0] = *(const uint32_t*)&Al[r0 * GP + c0];
                    afl[mi][1] = *(const uint32_t*)&Al[(r0 + 8) * GP + c0];
                    afl[mi][2] = *(const uint32_t*)&Al[r0 * GP + c0 + 8];
                    afl[mi][3] = *(const uint32_t*)&Al[(r0 + 8) * GP + c0 + 8];
                }
#pragma unroll
                for (int ni = 0; ni < 4; ni++) {
                    int r0 = n0w + ni * 8 + gid;
                    int c0 = kb + tig * 2;
                    bfh[ni][0] = *(const uint32_t*)&Bh[r0 * GP + c0];
                    bfh[ni][1] = *(const uint32_t*)&Bh[r0 * GP + c0 + 8];
                    bfl[ni][0] = *(const uint32_t*)&Bl[r0 * GP + c0];
                    bfl[ni][1] = *(const uint32_t*)&Bl[r0 * GP + c0 + 8];
                }
#pragma unroll
                for (int mi = 0; mi < 4; mi++)
#pragma unroll
                    for (int ni = 0; ni < 4; ni++) {
                        mma16816(acc[mi][ni], afh[mi], bfh[ni]);
                        mma16816(acc[mi][ni], afh[mi], bfl[ni]);
                        mma16816(acc[mi][ni], afl[mi], bfh[ni]);
                    }
            }
        }

        // store prefetched tile into other stage
        if (it + 1 < NIT) {
            __nv_bfloat16* base = gsm + (size_t)((it + 1) & 1) * GSTAGE;
            __nv_bfloat16* Ah = base;
            __nv_bfloat16* Al = base + GPLANE;
            __nv_bfloat16* Bh = base + 2 * GPLANE;
            __nv_bfloat16* Bl = base + 3 * GPLANE;
#pragma unroll
            for (int i = 0; i < 4; i++) {
                int off = (lrow + 32 * i) * GP + lcol;
                *(uint2*)&Ah[off] = make_uint2(pk_hi(ra[i].x, ra[i].y), pk_hi(ra[i].z, ra[i].w));
                *(uint2*)&Al[off] = make_uint2(pk_lo(ra[i].x, ra[i].y), pk_lo(ra[i].z, ra[i].w));
                *(uint2*)&Bh[off] = make_uint2(pk_hi(rb[i].x, rb[i].y), pk_hi(rb[i].z, rb[i].w));
                *(uint2*)&Bl[off] = make_uint2(pk_lo(rb[i].x, rb[i].y), pk_lo(rb[i].z, rb[i].w));
            }
        }
        __syncthreads();
    }

    // epilogue
#pragma unroll
    for (int mi = 0; mi < 4; mi++) {
#pragma unroll
        for (int ni = 0; ni < 4; ni++) {
            int row = m0 + m0w + mi * 16 + gid;
            int col = n0 + n0w + ni * 8 + tig * 2;
            float* c = acc[mi][ni];
            *(float2*)(C + (size_t)row * N + col)       = make_float2(c[0], c[1]);
            *(float2*)(C + (size_t)(row + 8) * N + col) = make_float2(c[2], c[3]);
        }
    }
}

// ---------------- RoPE tables (double precision, fast-math-proof) -----------
__global__ void rope_table_kernel()
{
    int t = blockIdx.x;      // 0..SEQ-1
    int i = threadIdx.x;     // 0..63
    double invf = exp(-((double)i / 64.0) * log(10000.0));
    double ang  = (double)t * invf;
    double sd, cd;
    sincos(ang, &sd, &cd);
    g_cos[t * 64 + i] = (float)cd;
    g_sin[t * 64 + i] = (float)sd;
}

// ---------------- RoPE apply (in-place on Q/K, layout [b,s,h,d]) ------------
__global__ __launch_bounds__(256) void rope_apply_kernel(const int* __restrict__ pos)
{
    int gid  = blockIdx.x * 256 + threadIdx.x;   // over MROWS*NH*64
    int i    = gid & 63;
    int hrow = gid >> 6;                         // (b*SEQ+s)*NH + h
    int s    = (hrow / NH) % SEQ;
    int p    = pos[s];
    float c  = g_cos[p * 64 + i];
    float sn = g_sin[p * 64 + i];
    float* ptr = (blockIdx.y ? g_K : g_Q) + (size_t)hrow * HD;
    float x1 = ptr[i];
    float x2 = ptr[i + 64];
    ptr[i]      = x1 * c - x2 * sn;
    ptr[i + 64] = x2 * c + x1 * sn;
}

// ---------------- Flash attention (fp32, causal, online softmax) ------------
#define FBM 64
#define FBN 64
#define QPITCH 132
#define PPITCH 68
#define FLASH_SMEM ((FBM*QPITCH*2 + FBN*PPITCH) * sizeof(float))

__global__ __launch_bounds__(256) void flash_kernel(
    const float* __restrict__ Q, const float* __restrict__ K,
    const float* __restrict__ V, float* __restrict__ CTX)
{
    extern __shared__ float sm[];
    float* Qs  = sm;                       // [64][132]
    float* KVs = sm + FBM * QPITCH;        // [64][132]
    float* Pst = KVs + FBM * QPITCH;       // [64][68]  P transposed: [col][row]

    const int tid = threadIdx.x;
    const int b   = blockIdx.y / NH;
    const int h   = blockIdx.y % NH;
    const int qt  = blockIdx.x;
    const int qm0 = qt * FBM;

    const int trow = tid >> 4;   // 0..15 -> rows trow*4..+3
    const int tcol = tid & 15;   // 0..15 -> score cols tcol*4..+3, out dims tcol*8..+7

    const float scale = 0.08838834764831845f;   // 1/sqrt(128)

    // load Q tile (scaled)
#pragma unroll
    for (int i = 0; i < 8; i++) {
        int f4  = tid + i * 256;
        int row = f4 >> 5;
        int col = (f4 & 31) << 2;
        size_t g = ((size_t)(b * SEQ + qm0 + row) * NH + h) * HD + col;
        float4 v = *(const float4*)(Q + g);
        v.x *= scale; v.y *= scale; v.z *= scale; v.w *= scale;
        *(float4*)&Qs[row * QPITCH + col] = v;
    }

    float m_i[4], l_i[4], accv[4][8];
#pragma unroll
    for (int i = 0; i < 4; i++) {
        m_i[i] = -3.0e38f; l_i[i] = 0.0f;
#pragma unroll
        for (int j = 0; j < 8; j++) accv[i][j] = 0.0f;
    }

    __syncthreads();

    for (int kt = 0; kt <= qt; kt++) {
        const int kn0 = kt * FBN;
        // load K tile
#pragma unroll
        for (int i = 0; i < 8; i++) {
            int f4  = tid + i * 256;
            int row = f4 >> 5;
            int col = (f4 & 31) << 2;
            size_t g = ((size_t)(b * SEQ + kn0 + row) * NH + h) * HD + col;
            *(float4*)&KVs[row * QPITCH + col] = *(const float4*)(K + g);
        }
        __syncthreads();

        // scores 4x4 per thread
        float sv[4][4];
#pragma unroll
        for (int i = 0; i < 4; i++)
#pragma unroll
            for (int j = 0; j < 4; j++) sv[i][j] = 0.0f;

        for (int d4 = 0; d4 < HD; d4 += 4) {
            float4 qv[4], kv[4];
#pragma unroll
            for (int i = 0; i < 4; i++)
                qv[i] = *(const float4*)&Qs[(trow * 4 + i) * QPITCH + d4];
#pragma unroll
            for (int j = 0; j < 4; j++)
                kv[j] = *(const float4*)&KVs[(tcol * 4 + j) * QPITCH + d4];
#pragma unroll
            for (int i = 0; i < 4; i++)
#pragma unroll
                for (int j = 0; j < 4; j++) {
                    sv[i][j] = fmaf(qv[i].x, kv[j].x, sv[i][j]);
                    sv[i][j] = fmaf(qv[i].y, kv[j].y, sv[i][j]);
                    sv[i][j] = fmaf(qv[i].z, kv[j].z, sv[i][j]);
                    sv[i][j] = fmaf(qv[i].w, kv[j].w, sv[i][j]);
                }
        }

        // causal mask (diagonal tile only)
        if (kt == qt) {
#pragma unroll
            for (int i = 0; i < 4; i++) {
                int qr = qm0 + trow * 4 + i;
#pragma unroll
                for (int j = 0; j < 4; j++) {
                    int kc = kn0 + tcol * 4 + j;
                    if (kc > qr) sv[i][j] += NEGBIG;
                }
            }
        }

        // online softmax update
        float p[4][4];
#pragma unroll
        for (int i = 0; i < 4; i++) {
            float rm = fmaxf(fmaxf(sv[i][0], sv[i][1]), fmaxf(sv[i][2], sv[i][3]));
#pragma unroll
            for (int off = 8; off > 0; off >>= 1)
                rm = fmaxf(rm, __shfl_xor_sync(0xffffffffu, rm, off));
            float mnew = fmaxf(m_i[i], rm);
            float corr = __expf(m_i[i] - mnew);
            float rs = 0.0f;
#pragma unroll
            for (int j = 0; j < 4; j++) {
                p[i][j] = __expf(sv[i][j] - mnew);
                rs += p[i][j];
            }
#pragma unroll
            for (int off = 8; off > 0; off >>= 1)
                rs += __shfl_xor_sync(0xffffffffu, rs, off);
            l_i[i] = l_i[i] * corr + rs;
            m_i[i] = mnew;
#pragma unroll
            for (int j = 0; j < 8; j++) accv[i][j] *= corr;
        }

        // store P transposed: Pst[col][row]
#pragma unroll
        for (int j = 0; j < 4; j++)
#pragma unroll
            for (int i = 0; i < 4; i++)
                Pst[(tcol * 4 + j) * PPITCH + trow * 4 + i] = p[i][j];

        __syncthreads();

        // load V tile over KVs
#pragma unroll
        for (int i = 0; i < 8; i++) {
            int f4  = tid + i * 256;
            int row = f4 >> 5;
            int col = (f4 & 31) << 2;
            size_t g = ((size_t)(b * SEQ + kn0 + row) * NH + h) * HD + col;
            *(float4*)&KVs[row * QPITCH + col] = *(const float4*)(V + g);
        }
        __syncthreads();

        // PV accumulate: rows trow*4..+3, dims tcol*8..+7
        for (int c = 0; c < FBN; c++) {
            float4 pv = *(const float4*)&Pst[c * PPITCH + trow * 4];
            float4 v0 = *(const float4*)&KVs[c * QPITCH + tcol * 8];
            float4 v1 = *(const float4*)&KVs[c * QPITCH + tcol * 8 + 4];
            float pr[4] = {pv.x, pv.y, pv.z, pv.w};
#pragma unroll
            for (int i = 0; i < 4; i++) {
                accv[i][0] = fmaf(pr[i], v0.x, accv[i][0]);
                accv[i][1] = fmaf(pr[i], v0.y, accv[i][1]);
                accv[i][2] = fmaf(pr[i], v0.z, accv[i][2]);
                accv[i][3] = fmaf(pr[i], v0.w, accv[i][3]);
                accv[i][4] = fmaf(pr[i], v1.x, accv[i][4]);
                accv[i][5] = fmaf(pr[i], v1.y, accv[i][5]);
                accv[i][6] = fmaf(pr[i], v1.z, accv[i][6]);
                accv[i][7] = fmaf(pr[i], v1.w, accv[i][7]);
            }
        }
        __syncthreads();   // protect KVs before next K load
    }

    // epilogue: O = acc / l  -> CTX [b,s,h,d]
#pragma unroll
    for (int i = 0; i < 4; i++) {
        float inv = 1.0f / l_i[i];
        int qr = qm0 + trow * 4 + i;
        size_t g = ((size_t)(b * SEQ + qr) * NH + h) * HD + tcol * 8;
        float4 o0 = make_float4(accv[i][0]*inv, accv[i][1]*inv, accv[i][2]*inv, accv[i][3]*inv);
        float4 o1 = make_float4(accv[i][4]*inv, accv[i][5]*inv, accv[i][6]*inv, accv[i][7]*inv);
        *(float4*)(CTX + g)     = o0;
        *(float4*)(CTX + g + 4) = o1;
    }
}

// ---------------- launch --------------------------------------------------
extern "C" void kernel_launch(void* const* d_in, const int* in_sizes, int n_in,
                              void* d_out, int out_size)
{
    const float* hs = (const float*)d_in[0];
    const float* Wq = (const float*)d_in[1];
    const float* Wk = (const float*)d_in[2];
    const float* Wv = (const float*)d_in[3];
    const float* Wo = (const float*)d_in[4];
    const int*   pos = (const int*)d_in[6];
    float* out = (float*)d_out;

    float *Qp, *Kp, *Vp, *Cp;
    cudaGetSymbolAddress((void**)&Qp, g_Q);
    cudaGetSymbolAddress((void**)&Kp, g_K);
    cudaGetSymbolAddress((void**)&Vp, g_V);
    cudaGetSymbolAddress((void**)&Cp, g_CTX);

    cudaFuncSetAttribute(flash_kernel,
                         cudaFuncAttributeMaxDynamicSharedMemorySize,
                         (int)FLASH_SMEM);
    cudaFuncSetAttribute(gemm_bf16x2_nt,
                         cudaFuncAttributeMaxDynamicSharedMemorySize,
                         (int)GEMM_SMEM);

    dim3 ggrid(HID / GBN, MROWS / GBM);   // (16, 32)
    dim3 gblk(256);

    gemm_bf16x2_nt<<<ggrid, gblk, GEMM_SMEM>>>(hs, Wq, Qp, MROWS, HID, HID);
    gemm_bf16x2_nt<<<ggrid, gblk, GEMM_SMEM>>>(hs, Wk, Kp, MROWS, HID, HID);
    gemm_bf16x2_nt<<<ggrid, gblk, GEMM_SMEM>>>(hs, Wv, Vp, MROWS, HID, HID);

    rope_table_kernel<<<SEQ, 64>>>();
    rope_apply_kernel<<<dim3((MROWS * NH * 64) / 256, 2), 256>>>(pos);

    flash_kernel<<<dim3(SEQ / FBM, BSZ * NH), 256, FLASH_SMEM>>>(Qp, Kp, Vp, Cp);

    gemm_bf16x2_nt<<<ggrid, gblk, GEMM_SMEM>>>(Cp, Wo, out, MROWS, HID, HID);
}